// round 11
// baseline (speedup 1.0000x reference)
#include <cuda_runtime.h>
#include <cstdint>

// Problem geometry (fixed: GRID = (32,32,32), 6 channels)
#define NCELL 32768
#define CMASK 32767          // NCELL-1: power-of-two address clamp
#define NCH   6
#define NCTA  128            // all CTAs co-resident
#define NTHR  256            // one thread per cell
#define FLAG_STRIDE 64       // 256B apart -> distinct L2 slices
#define NV4   (NCH * NCELL / 4)
// Freeze-token ring: one write-once slot per superstep, 8 replicas each.
#define NSLOT 160            // >= ceil(300/2)+2 supersteps
#define NREP  8              // 16 CTAs poll each replica
#define TOK_STRIDE 32        // 128B apart

// Persistent device scratch (allocation-free). All sync state re-zeroed at the
// top of each launch, published by the one-time init barrier -> deterministic
// across calls / graph replays.
__device__ __align__(16) float g_po[2][NCH * NCELL];     // double-buffered po = clip(D·phi)
__device__ __align__(16) float g_frozen[NCH * NCELL];    // frozen phi for tail fill
__device__ volatile unsigned g_flags[NCTA * FLAG_STRIDE];// per-CTA superstep counters
__device__ volatile unsigned g_tok[NSLOT * NREP * TOK_STRIDE]; // write-once tokens
__device__ int      g_tail_start;
__device__ int      g_maxit;
// init-barrier state (classic; gen relative -> replay-safe without reset)
__device__ unsigned g_ib_arrive;
__device__ volatile unsigned g_ib_gen;

__device__ __forceinline__ float clip01(float a) {
    return fminf(fmaxf(a, 0.0f), 1.0f);
}

// Scoped release store: orders all prior (CTA-cumulative via bar.sync) writes
// before the flag becomes visible at gpu scope. Cheaper than MEMBAR.GPU + ST.
__device__ __forceinline__ void st_release_gpu(volatile unsigned* p, unsigned v) {
    asm volatile("st.release.gpu.global.u32 [%0], %1;"
                 :: "l"((unsigned*)p), "r"(v) : "memory");
}

// Classic atomic grid barrier — used ONCE per launch to publish init state.
__device__ __forceinline__ void init_grid_sync()
{
    __syncthreads();
    if (threadIdx.x == 0) {
        __threadfence();
        unsigned gen = g_ib_gen;
        unsigned old = atomicAdd(&g_ib_arrive, 1u);
        if (old == NCTA - 1) {
            atomicExch(&g_ib_arrive, 0u);
            __threadfence();
            g_ib_gen = gen + 1u;
        } else {
            while (g_ib_gen == gen) { }
        }
        __threadfence();
    }
    __syncthreads();
}

__global__ void __launch_bounds__(NTHR, 1)
flash_wave_kernel(const float* __restrict__ D,
                  const int* __restrict__ p_sx, const int* __restrict__ p_sy,
                  const int* __restrict__ p_sz, const int* __restrict__ p_ex,
                  const int* __restrict__ p_ey, const int* __restrict__ p_ez,
                  const int* __restrict__ p_mi,
                  float* __restrict__ out)
{
    __shared__ int   s_par[7];
    __shared__ int   s_flags;
    __shared__ int   s_nb[12];      // neighbor CTA ids (halo distance <= 2)
    __shared__ int   s_nnb;
    __shared__ float s_probe[2];    // target-cell sums (target CTA only)

    const int bid = blockIdx.x;
    const int c   = bid * NTHR + threadIdx.x;   // this thread's cell

    if (threadIdx.x == 0) {
        s_par[0] = *p_sx; s_par[1] = *p_sy; s_par[2] = *p_sz;
        s_par[3] = *p_ex; s_par[4] = *p_ey; s_par[5] = *p_ez;
        s_par[6] = *p_mi;
        g_flags[bid * FLAG_STRIDE] = 0u;        // reset my superstep counter

        // Neighbor CTA set: CTA = (X = bid>>2, Y-octant = bid&3), 8 y's, full z.
        // Distance-2 halo touches (X±2,Y), (X±1,Y+{-1,0,1}), (X,Y±1).
        const int X = bid >> 2, Y = bid & 3;
        const int off[10][2] = {{-2,0},{2,0},{-1,-1},{-1,0},{-1,1},
                                { 1,-1},{1,0},{ 1, 1},{ 0,-1},{0,1}};
        int n = 0;
        for (int i = 0; i < 10; i++) {
            int Xn = X + off[i][0], Yn = Y + off[i][1];
            if ((unsigned)Xn < 32u && (unsigned)Yn < 4u)
                s_nb[n++] = Xn * 4 + Yn;
        }
        s_nnb = n;
    }
    // Zero all token slots (write-once per launch; 1280 words).
    if (c < NSLOT * NREP) g_tok[c * TOK_STRIDE] = 0u;
    __syncthreads();

    const int srcc  = (s_par[0] << 10) + (s_par[1] << 5) + s_par[2];
    const int ct    = (s_par[3] << 10) + (s_par[4] << 5) + s_par[5];
    const int maxit = s_par[6];
    const int tgt_cta = ct >> 8;                // CTA owning the target cell

    if (c == 0) {
        g_maxit = maxit;
        g_tail_start = maxit;   // default: no tail
    }

    const int x = c >> 10;
    const int y = (c >> 5) & 31;
    const int z = c & 31;

    // Channel ch's SOURCE offset (gather form): flattened deltas.
    // nxt[0,x]=po[0,x-1]; nxt[1,x]=po[1,x+1]; etc.
    const int dx[6] = {-1, 1, 0, 0, 0, 0};
    const int dy[6] = { 0, 0,-1, 1, 0, 0};
    const int dz[6] = { 0, 0, 0, 0,-1, 1};
    const int doff[6] = {-1024, 1024, -32, 32, -1, 1};

    // Own active_D rows (36 regs): D[o][i][c] + 0.95
    float Dr[36];
    #pragma unroll
    for (int k = 0; k < 36; k++) Dr[k] = D[k * NCELL + c] + 0.95f;

    // Level-1 gather validity mask. Addresses are computed on the fly as
    // (c + doff) & CMASK — invalid gathers land on SOME in-bounds cell and are
    // zeroed by m1 / Dn, so no address registers are needed.
    float m1[6];
    #pragma unroll
    for (int ch = 0; ch < 6; ch++) {
        int x1 = x + dx[ch], y1 = y + dy[ch], z1 = z + dz[ch];
        bool ok = ((unsigned)x1 < 32u) & ((unsigned)y1 < 32u) & ((unsigned)z1 < 32u);
        m1[ch] = ok ? 1.0f : 0.0f;
    }

    // Neighbor-D rows with all boundary conditions folded in as zeros.
    // Dn[ch][i] = D[ch][i](s_ch) + 0.95 if both hops stay in-grid, else 0.
    float Dn[36];
    #pragma unroll
    for (int ch = 0; ch < 6; ch++) {
        int x1 = x + dx[ch], y1 = y + dy[ch], z1 = z + dz[ch];
        bool ok1 = ((unsigned)x1 < 32u) & ((unsigned)y1 < 32u) & ((unsigned)z1 < 32u);
        int s1i = ok1 ? ((x1 << 10) | (y1 << 5) | z1) : c;
        #pragma unroll
        for (int i = 0; i < 6; i++) {
            int x2 = x1 + dx[i], y2 = y1 + dy[i], z2 = z1 + dz[i];
            bool ok2 = ok1 & ((unsigned)x2 < 32u) & ((unsigned)y2 < 32u) & ((unsigned)z2 < 32u);
            Dn[ch * 6 + i] = ok2 ? (D[(ch * 6 + i) * NCELL + s1i] + 0.95f) : 0.0f;
        }
    }

    // Init: phi0 = zeros except all 6 channels = 1 at source; history[0] = phi0.
    const float v0 = (c == srcc) ? 1.0f : 0.0f;
    #pragma unroll
    for (int i = 0; i < 6; i++) __stcs(&out[i * NCELL + c], v0);

    // po(0) at own cell, kept in regs + stored to g_po[0].
    float po_reg[6];
    #pragma unroll
    for (int o = 0; o < 6; o++) {
        float a = Dr[o * 6] * v0;
        #pragma unroll
        for (int i = 1; i < 6; i++) a = fmaf(Dr[o * 6 + i], v0, a);
        po_reg[o] = clip01(a);
    }
    #pragma unroll
    for (int o = 0; o < 6; o++) g_po[0][o * NCELL + c] = po_reg[o];

    init_grid_sync();   // publish po(0) + zeroed flags/tokens grid-wide

    int t = 0;   // phi(t) = last committed state; history[0..t] written
    int p = 0;   // g_po[p] holds po(t)
    int k = 1;   // superstep counter (flag value / token slot)

    for (;;) {
        if (t + 1 >= maxit) break;

        const float* __restrict__ po_rd = g_po[p];

        // ---- v1 = phi(t+1): one gather per channel (L2, never stale) ----
        float v1[6];
        #pragma unroll
        for (int ch = 0; ch < 6; ch++)
            v1[ch] = m1[ch] * __ldcg(&po_rd[ch * NCELL + ((c + doff[ch]) & CMASK)]);

        if (t + 1 == maxit - 1) {
            // Last slab: write history[t+1] and finish (no tail).
            float* h1 = out + (size_t)(t + 1) * (NCH * NCELL);
            #pragma unroll
            for (int ch = 0; ch < 6; ch++) __stcs(&h1[ch * NCELL + c], v1[ch]);
            break;
        }

        // ---- v2 = phi(t+2): recompute neighbors' po(t+1) from po(t) ----
        // v2[ch] = clip( sum_i Dn[ch][i] * po(t)[i]((c + doff[ch] + doff[i]) & CMASK) );
        // the i == ch^1 term lands back on c -> register po_reg.
        float v2[6];
        #pragma unroll
        for (int ch = 0; ch < 6; ch++) {
            float a = 0.0f;
            #pragma unroll
            for (int i = 0; i < 6; i++) {
                float g = (i == (ch ^ 1)) ? po_reg[i]
                        : __ldcg(&po_rd[i * NCELL + ((c + doff[ch] + doff[i]) & CMASK)]);
                if (i == 0) a = Dn[ch * 6] * g;
                else        a = fmaf(Dn[ch * 6 + i], g, a);
            }
            v2[ch] = clip01(a);
        }

        // Target thread publishes probe sums to ITS CTA's smem.
        if (c == ct) {
            s_probe[0] = v1[0] + v1[1] + v1[2] + v1[3] + v1[4] + v1[5];
            s_probe[1] = v2[0] + v2[1] + v2[2] + v2[3] + v2[4] + v2[5];
        }

        // po(t+2) at own cell -> other buffer (before flag publish).
        float po2[6];
        #pragma unroll
        for (int o = 0; o < 6; o++) {
            float a = Dr[o * 6] * v2[0];
            #pragma unroll
            for (int i = 1; i < 6; i++) a = fmaf(Dr[o * 6 + i], v2[i], a);
            po2[o] = clip01(a);
        }
        {
            float* __restrict__ po_wr = g_po[p ^ 1];
            #pragma unroll
            for (int o = 0; o < 6; o++) po_wr[o * NCELL + c] = po2[o];
        }

        // ---- Publish: token slot k (target CTA only), then flag = k ----
        __syncthreads();   // all po2 stores + s_probe done (CTA-cumulative)
        if (threadIdx.x == 0) {
            if (bid == tgt_cta) {
                // Write-once token for THIS superstep: nonzero since k >= 1.
                unsigned pk = ((unsigned)k << 2)
                            | (s_probe[0] > 0.01f ? 2u : 0u)
                            | (s_probe[1] > 0.01f ? 1u : 0u);
                #pragma unroll
                for (int r = 0; r < NREP; r++)
                    g_tok[(k * NREP + r) * TOK_STRIDE] = pk;
            }
            // Release store: orders po2 (and token) before the flag.
            st_release_gpu(&g_flags[bid * FLAG_STRIDE], (unsigned)k);
        }

        // history[t+1] = v1 and SPECULATIVE history[t+2] = v2 — both overlap
        // with the waits below. If the wave froze at t+1, the tail kernel
        // (t0 = t+2) overwrites the speculative slab; kernel-boundary ordering
        // makes that safe.
        {
            float* h1 = out + (size_t)(t + 1) * (NCH * NCELL);
            float* h2 = out + (size_t)(t + 2) * (NCH * NCELL);
            #pragma unroll
            for (int ch = 0; ch < 6; ch++) __stcs(&h1[ch * NCELL + c], v1[ch]);
            #pragma unroll
            for (int ch = 0; ch < 6; ch++) __stcs(&h2[ch * NCELL + c], v2[ch]);
        }

        // ---- Wait: neighbors >= k, and the EXACT superstep-k freeze token.
        // Leader-warp lanes poll in parallel; exact slot -> uniform decision.
        if (threadIdx.x < 32) {
            const int nn = s_nnb;
            if ((int)threadIdx.x < nn) {
                volatile unsigned* w = &g_flags[s_nb[threadIdx.x] * FLAG_STRIDE];
                while (*w < (unsigned)k) { }
            } else if (threadIdx.x == 30) {
                volatile unsigned* w = &g_tok[(k * NREP + (bid & (NREP - 1))) * TOK_STRIDE];
                unsigned pk;
                do { pk = *w; } while (pk == 0u);
                s_flags = (int)(pk & 3u);
            }
            __syncwarp();
        }
        __syncthreads();
        const int fl = s_flags;

        if (fl & 2) {
            // Reached at t+1: frozen phi = v1; slabs [t+2, maxit) via tail
            // (overwrites the speculative t+2 slab).
            #pragma unroll
            for (int ch = 0; ch < 6; ch++) g_frozen[ch * NCELL + c] = v1[ch];
            if (c == 0) g_tail_start = t + 2;
            break;
        }

        if (fl & 1) {
            // Reached at t+2: frozen phi = v2; slabs [t+3, maxit) via tail.
            #pragma unroll
            for (int ch = 0; ch < 6; ch++) g_frozen[ch * NCELL + c] = v2[ch];
            if (c == 0) g_tail_start = t + 3;
            break;
        }

        #pragma unroll
        for (int o = 0; o < 6; o++) po_reg[o] = po2[o];
        p ^= 1;
        t += 2;
        k += 1;
    }
}

// Tail fill: slabs [g_tail_start, g_maxit) all equal g_frozen.
// One load, many stores: each thread owns one float4 of the slab, loads it
// once, streams it into a contiguous range of slabs (pure-write).
// Grid: x = 192 CTAs x 256 thr = 49152 threads (one per float4), y = 6 chunks.
__global__ void __launch_bounds__(256)
tail_fill_kernel(float* __restrict__ out)
{
    const int t0 = g_tail_start;
    const int mi = g_maxit;
    const int nslab = mi - t0;
    if (nslab <= 0) return;

    const int idx = blockIdx.x * blockDim.x + threadIdx.x;
    if (idx >= NV4) return;

    const float4 val = __ldcg(&reinterpret_cast<const float4*>(g_frozen)[idx]);
    float4* __restrict__ dst4 = reinterpret_cast<float4*>(out);

    const int per = (nslab + gridDim.y - 1) / gridDim.y;
    const int u0  = t0 + blockIdx.y * per;
    const int u1  = (u0 + per < mi) ? (u0 + per) : mi;
    for (int u = u0; u < u1; u++)
        __stcs(&dst4[(size_t)u * NV4 + idx], val);
}

extern "C" void kernel_launch(void* const* d_in, const int* in_sizes, int n_in,
                              void* d_out, int out_size)
{
    const float* D  = (const float*)d_in[0];
    const int*   sx = (const int*)d_in[1];
    const int*   sy = (const int*)d_in[2];
    const int*   sz = (const int*)d_in[3];
    const int*   ex = (const int*)d_in[4];
    const int*   ey = (const int*)d_in[5];
    const int*   ez = (const int*)d_in[6];
    const int*   mi = (const int*)d_in[7];

    flash_wave_kernel<<<NCTA, NTHR>>>(D, sx, sy, sz, ex, ey, ez, mi, (float*)d_out);
    tail_fill_kernel<<<dim3(192, 6), 256>>>((float*)d_out);
}